// round 4
// baseline (speedup 1.0000x reference)
#include <cuda_runtime.h>

// ---------------------------------------------------------------------------
// Quantized LSTM (int8 fixed-point fake-quant with per-step runtime po2 scales)
//   x     : [B=1024, T=1024, I=10]  fp32
//   W_ih  : [4H=80, I=10]           fp32
//   W_hh  : [4H=80, H=20]           fp32
//   out   : [B, T, H=20]            fp32
//
// Batches are coupled per step only through global max-abs reductions (quant
// scales). Persistent kernel: 128 blocks x 640 threads, software grid barrier
// (4 per step), per-step pre-zeroed global max cells (no reset races).
// ---------------------------------------------------------------------------

#define GB       128          // grid blocks (<= SM count -> co-resident)
#define BPB      8            // batches per block (128*8 = 1024)
#define NT       640          // threads per block = 80 gates * 8 batches
#define T_STEPS  1024
#define NI       10
#define NH       20
#define NG       80

__device__ unsigned int g_ctr;                 // barrier arrival counter
__device__ unsigned int g_max[T_STEPS * 7];    // per-step max cells (abs fp32 bits)

__global__ void qlstm_init() {
    int i = blockIdx.x * blockDim.x + threadIdx.x;
    if (i == 0) g_ctr = 0u;
    for (int k = i; k < T_STEPS * 7; k += blockDim.x * gridDim.x) g_max[k] = 0u;
}

// scale = 2^ceil(log2(max(m,1e-8)))/128, computed bit-exactly.
// frexpf: m = f * 2^e, f in [0.5, 1). ceil(log2 m) = e unless f==0.5 -> e-1.
__device__ __forceinline__ void po2(unsigned int mbits, float& s, float& inv) {
    float m = fmaxf(__uint_as_float(mbits), 1e-8f);
    int e;
    float f = frexpf(m, &e);
    int k = (f == 0.5f) ? (e - 1) : e;
    s   = ldexpf(1.0f, k - 7);
    inv = ldexpf(1.0f, 7 - k);
}

// fake-quant: clip(round(x/s), -128, 127) * s   (round = half-to-even, exact po2 scaling)
__device__ __forceinline__ float fq1(float x, float s, float inv) {
    float q = rintf(x * inv);
    q = fminf(fmaxf(q, -128.0f), 127.0f);
    return q * s;
}

__device__ __forceinline__ float warp_max(float v) {
#pragma unroll
    for (int o = 16; o; o >>= 1) v = fmaxf(v, __shfl_xor_sync(0xffffffffu, v, o));
    return v;
}

__global__ void __launch_bounds__(NT, 1) qlstm_main(
    const float* __restrict__ x,
    const float* __restrict__ Wih,
    const float* __restrict__ Whh,
    float* __restrict__ out)
{
    __shared__ float        sh_h[BPB * NH];     // quantized h state [b][j]
    __shared__ float        sh_x[BPB * NI];     // current-step x [b][i]
    __shared__ float        sh_act[NG * BPB];   // quantized activations, index = tid
    __shared__ unsigned int sh_red[4];          // block-level max cells
    __shared__ float        sh_s[4], sh_i[4];   // broadcast scales / inverse scales

    const int tid   = threadIdx.x;
    const int g     = tid / BPB;     // gate row 0..79 (g-major: each warp = 1 gate group)
    const int b     = tid % BPB;     // local batch 0..7
    const int gr    = tid / 160;     // gate group 0..3 (i, f, g~, o) -- warp-uniform
    const int wlane = tid & 31;

    if (tid < 4) sh_red[tid] = 0u;
    if (tid < BPB * NH) sh_h[tid] = 0.0f;
    __syncthreads();

    // ---- weight scale: shared max over both weight tensors (block-local, tiny) ----
    float wm = 0.0f;
    for (int k = tid; k < NG * NI; k += NT) wm = fmaxf(wm, fabsf(Wih[k]));
    for (int k = tid; k < NG * NH; k += NT) wm = fmaxf(wm, fabsf(Whh[k]));
    wm = warp_max(wm);
    if (wlane == 0) atomicMax(&sh_red[0], __float_as_uint(wm));
    __syncthreads();
    float ws, wsi;
    po2(sh_red[0], ws, wsi);
    __syncthreads();
    if (tid == 0) sh_red[0] = 0u;     // reset before loop (covered by sync below)

    // quantized weights for this thread's gate row -> registers (loaded once)
    float wi[NI], wh[NH];
#pragma unroll
    for (int i2 = 0; i2 < NI; i2++) wi[i2] = fq1(Wih[g * NI + i2], ws, wsi);
#pragma unroll
    for (int j2 = 0; j2 < NH; j2++) wh[j2] = fq1(Whh[g * NH + j2], ws, wsi);

    float c = 0.0f;                   // cell state, owned by threads tid<160 (b,j)

    // ---- x staging: distance-2 prefetch through smem ----
    const int xb = tid / NI, xi = tid % NI;   // valid when tid < 80
    float xr = 0.0f;
    if (tid < BPB * NI) {
        sh_x[tid] = x[((size_t)(blockIdx.x * BPB + xb) * T_STEPS + 0) * NI + xi];
        xr        = x[((size_t)(blockIdx.x * BPB + xb) * T_STEPS + 1) * NI + xi];
    }
    __syncthreads();

    for (int t = 0; t < T_STEPS; ++t) {
        // ================= phase 1: gates = xW_i^T + hW_h^T, global max =================
        float pre = 0.0f;
#pragma unroll
        for (int i2 = 0; i2 < NI; i2++) pre = fmaf(sh_x[b * NI + i2], wi[i2], pre);
#pragma unroll
        for (int j2 = 0; j2 < NH; j2++) pre = fmaf(sh_h[b * NH + j2], wh[j2], pre);

        float a = warp_max(fabsf(pre));
        if (wlane == 0) atomicMax(&sh_red[0], __float_as_uint(a));
        __syncthreads();
        if (tid == 0) {
            unsigned int v = sh_red[0]; sh_red[0] = 0u;
            atomicMax(&g_max[t * 7 + 0], v);
            __threadfence();
            atomicAdd(&g_ctr, 1u);
            unsigned int tgt = ((unsigned)t * 4u + 1u) * GB;
            while (*((volatile unsigned int*)&g_ctr) < tgt) { }
            po2(__ldcg(&g_max[t * 7 + 0]), sh_s[0], sh_i[0]);
        }
        __syncthreads();
        float gq = fq1(pre, sh_s[0], sh_i[0]);

        // ================= phase 2: activations, per-group maxes (1 sync) ==============
        float act = (gr == 2) ? tanhf(gq) : (1.0f / (1.0f + expf(-gq)));
        a = warp_max(fabsf(act));
        if (wlane == 0) atomicMax(&sh_red[gr], __float_as_uint(a));
        __syncthreads();
        if (tid == 0) {
#pragma unroll
            for (int k = 0; k < 4; k++) {
                unsigned int v = sh_red[k]; sh_red[k] = 0u;
                atomicMax(&g_max[t * 7 + 1 + k], v);
            }
            __threadfence();
            atomicAdd(&g_ctr, 1u);
            unsigned int tgt = ((unsigned)t * 4u + 2u) * GB;
            while (*((volatile unsigned int*)&g_ctr) < tgt) { }
#pragma unroll
            for (int k = 0; k < 4; k++)
                po2(__ldcg(&g_max[t * 7 + 1 + k]), sh_s[k], sh_i[k]);
        }
        __syncthreads();
        sh_act[tid] = fq1(act, sh_s[gr], sh_i[gr]);
        __syncthreads();

        // ================= phase 3: c = f*c + i*g~, max|tanh(c)| =======================
        float tc = 0.0f, oq = 0.0f;
        if (tid < 160) {
            float iq  = sh_act[tid];
            float ffq = sh_act[tid + 160];
            float ggq = sh_act[tid + 320];
            oq        = sh_act[tid + 480];
            c  = ffq * c + iq * ggq;
            tc = tanhf(c);
        }
        a = warp_max(fabsf(tc));
        if (wlane == 0) atomicMax(&sh_red[0], __float_as_uint(a));
        __syncthreads();
        if (tid == 0) {
            unsigned int v = sh_red[0]; sh_red[0] = 0u;
            atomicMax(&g_max[t * 7 + 5], v);
            __threadfence();
            atomicAdd(&g_ctr, 1u);
            unsigned int tgt = ((unsigned)t * 4u + 3u) * GB;
            while (*((volatile unsigned int*)&g_ctr) < tgt) { }
            po2(__ldcg(&g_max[t * 7 + 5]), sh_s[0], sh_i[0]);
        }
        __syncthreads();

        // ================= phase 4: h_pre = o_q * q(tanh c), max, quantize =============
        float hp = 0.0f;
        if (tid < 160) hp = oq * fq1(tc, sh_s[0], sh_i[0]);
        a = warp_max(fabsf(hp));
        if (wlane == 0) atomicMax(&sh_red[1], __float_as_uint(a));
        __syncthreads();
        if (tid == 0) {
            unsigned int v = sh_red[1]; sh_red[1] = 0u;
            atomicMax(&g_max[t * 7 + 6], v);
            __threadfence();
            atomicAdd(&g_ctr, 1u);
            unsigned int tgt = ((unsigned)t * 4u + 4u) * GB;
            while (*((volatile unsigned int*)&g_ctr) < tgt) { }
            po2(__ldcg(&g_max[t * 7 + 6]), sh_s[1], sh_i[1]);
        }
        __syncthreads();
        if (tid < 160) {
            float hq = fq1(hp, sh_s[1], sh_i[1]);
            sh_h[b * NH + g] = hq;    // g == hidden index j for tid<160
            out[((size_t)(blockIdx.x * BPB + b) * T_STEPS + t) * NH + g] = hq;
        }
        // stage next-step x, then publish h + x together
        if (tid < BPB * NI && t + 1 < T_STEPS) sh_x[tid] = xr;
        __syncthreads();
        if (tid < BPB * NI && t + 2 < T_STEPS)
            xr = x[((size_t)(blockIdx.x * BPB + xb) * T_STEPS + (t + 2)) * NI + xi];
    }
}

extern "C" void kernel_launch(void* const* d_in, const int* in_sizes, int n_in,
                              void* d_out, int out_size) {
    (void)in_sizes; (void)n_in; (void)out_size;
    qlstm_init<<<64, 256>>>();
    qlstm_main<<<GB, NT>>>((const float*)d_in[0],
                           (const float*)d_in[1],
                           (const float*)d_in[2],
                           (float*)d_out);
}

// round 5
// speedup vs baseline: 1.0423x; 1.0423x over previous
#include <cuda_runtime.h>

// ---------------------------------------------------------------------------
// Quantized LSTM, 2 grid barriers per step (steady state):
//   barrier B: signed min/max of gate pre-activations per group
//              -> gates scale AND all 4 activation scales (monotonicity)
//   barrier C: max|tanh(c)| + speculative max|o_q * fq(tanh c, s_pred)|
//              -> tanh scale + h scale in one round (fallback barrier if the
//                 tanh-scale prediction misses; rare)
// Barrier protocol: parallel relaxed atom.max cells -> acq_rel counter add ->
// last arriver reads cells, resets, publishes packed exponents via one
// release-store u64 that pollers acquire-load (tag = barrier index).
// ---------------------------------------------------------------------------

#define GB       128
#define BPB      8
#define NT       640
#define T_STEPS  1024
#define NI       10
#define NH       20
#define NG       80

__device__ __align__(128) unsigned g_ctr[32];
__device__ __align__(128) unsigned g_cellsB[32];     // [0..3] max pre/group (mapped), [4] max -pre (g grp), [5] max -pre (all)
__device__ __align__(128) unsigned g_cellsC[32];     // [0] max|tc|, [1] max|hp_spec|, [2] max|hp_fallback|
__device__ __align__(128) unsigned long long g_bcB[16];
__device__ __align__(128) unsigned long long g_bcC[16];
__device__ __align__(128) unsigned long long g_bcD[16];

__global__ void qlstm_init() {
    int i = threadIdx.x;
    if (i < 32) { g_ctr[i] = 0u; g_cellsB[i] = 0u; g_cellsC[i] = 0u; }
    if (i < 16) { g_bcB[i] = 0ull; g_bcC[i] = 0ull; g_bcD[i] = 0ull; }
}

// ---- order-preserving float<->uint key (signed max via unsigned atomicMax) ----
__device__ __forceinline__ unsigned mapf(float f) {
    unsigned u = __float_as_uint(f);
    return (u & 0x80000000u) ? ~u : (u | 0x80000000u);
}
__device__ __forceinline__ float unmapf(unsigned u) {
    return __uint_as_float((u & 0x80000000u) ? (u & 0x7FFFFFFFu) : ~u);
}

// ---- k = ceil(log2(max(m,1e-8))); scale = 2^(k-7), inv = 2^(7-k) ----
__device__ __forceinline__ int po2k(float m) {
    m = fmaxf(m, 1e-8f);
    int e; float f = frexpf(m, &e);
    return (f == 0.5f) ? (e - 1) : e;
}
__device__ __forceinline__ float sc(int k)    { return __uint_as_float((unsigned)(k + 120) << 23); }
__device__ __forceinline__ float scinv(int k) { return __uint_as_float((unsigned)(134 - k) << 23); }

__device__ __forceinline__ float fq1(float x, float s, float inv) {
    float q = rintf(x * inv);
    q = fminf(fmaxf(q, -128.0f), 127.0f);
    return q * s;
}
__device__ __forceinline__ float sigm(float x) { return 1.0f / (1.0f + expf(-x)); }

__device__ __forceinline__ unsigned warp_max_u(unsigned v) {
#pragma unroll
    for (int o = 16; o; o >>= 1) v = max(v, __shfl_xor_sync(0xffffffffu, v, o));
    return v;
}

// ---- scoped memory ops (generic address space) ----
__device__ __forceinline__ unsigned atom_max_rlx(unsigned* p, unsigned v) {
    unsigned old;
    asm volatile("atom.relaxed.gpu.max.u32 %0,[%1],%2;" : "=r"(old) : "l"(p), "r"(v) : "memory");
    return old;
}
__device__ __forceinline__ unsigned atom_add_acqrel(unsigned* p, unsigned v) {
    unsigned old;
    asm volatile("atom.acq_rel.gpu.add.u32 %0,[%1],%2;" : "=r"(old) : "l"(p), "r"(v) : "memory");
    return old;
}
__device__ __forceinline__ unsigned ld_rlx(const unsigned* p) {
    unsigned v; asm volatile("ld.relaxed.gpu.u32 %0,[%1];" : "=r"(v) : "l"(p) : "memory"); return v;
}
__device__ __forceinline__ void st_rlx(unsigned* p, unsigned v) {
    asm volatile("st.relaxed.gpu.u32 [%0],%1;" :: "l"(p), "r"(v) : "memory");
}
__device__ __forceinline__ unsigned long long ld_acq64(const unsigned long long* p) {
    unsigned long long v; asm volatile("ld.acquire.gpu.u64 %0,[%1];" : "=l"(v) : "l"(p) : "memory"); return v;
}
__device__ __forceinline__ void st_rel64(unsigned long long* p, unsigned long long v) {
    asm volatile("st.release.gpu.u64 [%0],%1;" :: "l"(p), "l"(v) : "memory");
}

__global__ void __launch_bounds__(NT, 1) qlstm_main(
    const float* __restrict__ x,
    const float* __restrict__ Wih,
    const float* __restrict__ Whh,
    float* __restrict__ out)
{
    __shared__ float        sh_h[BPB * NH];
    __shared__ float        sh_x[BPB * NI];
    __shared__ float        sh_act[NG * BPB];
    __shared__ unsigned     sh_red[12];   // B:[0..7]  C:[8,9]  D:[10]  dump:[11]
    __shared__ int          sh_k[6];

    const int tid  = threadIdx.x;
    const int g    = tid / BPB;          // gate row 0..79
    const int b    = tid % BPB;          // local batch 0..7
    const int gr   = tid / 160;          // gate group 0..3 (warp-uniform)
    const int lane = tid & 31;
    const int wid  = tid >> 5;

    if (tid < 12) sh_red[tid] = 0u;
    if (tid < BPB * NH) sh_h[tid] = 0.0f;
    __syncthreads();

    // ---- weight scale (shared over both tensors; block-local, once) ----
    {
        float wm = 0.0f;
        for (int k = tid; k < NG * NI; k += NT) wm = fmaxf(wm, fabsf(Wih[k]));
        for (int k = tid; k < NG * NH; k += NT) wm = fmaxf(wm, fabsf(Whh[k]));
        unsigned u = warp_max_u(__float_as_uint(wm));
        if (lane == 0) atomicMax(&sh_red[11], u);
        __syncthreads();
    }
    int kw = po2k(__uint_as_float(sh_red[11]));
    float ws = sc(kw), wsi = scinv(kw);
    __syncthreads();
    if (tid == 11) sh_red[11] = 0u;

    float wi[NI], wh[NH];
#pragma unroll
    for (int i2 = 0; i2 < NI; i2++) wi[i2] = fq1(Wih[g * NI + i2], ws, wsi);
#pragma unroll
    for (int j2 = 0; j2 < NH; j2++) wh[j2] = fq1(Whh[g * NH + j2], ws, wsi);

    float c = 0.0f;
    int   k_pred = 0;        // predicted tanh(c) scale exponent
    unsigned nbar = 0;       // barrier index (used by tid0 only)

    const int xb = tid / NI, xi = tid % NI;
    float xr = 0.0f;
    if (tid < BPB * NI) {
        sh_x[tid] = x[((size_t)(blockIdx.x * BPB + xb) * T_STEPS + 0) * NI + xi];
        xr        = x[((size_t)(blockIdx.x * BPB + xb) * T_STEPS + 1) * NI + xi];
    }
    __syncthreads();

    for (int t = 0; t < T_STEPS; ++t) {
        // ============ phase B: gate pre-activations + signed min/max reduce ============
        float pre = 0.0f;
#pragma unroll
        for (int i2 = 0; i2 < NI; i2++) pre = fmaf(sh_x[b * NI + i2], wi[i2], pre);
#pragma unroll
        for (int j2 = 0; j2 < NH; j2++) pre = fmaf(sh_h[b * NH + j2], wh[j2], pre);

        unsigned kpw = warp_max_u(mapf(pre));
        unsigned knw = warp_max_u(mapf(-pre));
        if (lane == 0) { atomicMax(&sh_red[gr], kpw); atomicMax(&sh_red[4 + gr], knw); }
        __syncthreads();

        if (wid == 0) {
            unsigned v = (lane < 8) ? sh_red[lane] : 0u;
            __syncwarp();
            if (lane < 8) sh_red[lane] = 0u;
            unsigned g4 = __shfl_sync(0xffffffffu, v, 4);
            unsigned g5 = __shfl_sync(0xffffffffu, v, 5);
            unsigned g6 = __shfl_sync(0xffffffffu, v, 6);
            unsigned g7 = __shfl_sync(0xffffffffu, v, 7);
            int cell = -1; unsigned myv = 0;
            if (lane < 4)       { myv = v; cell = lane; }
            else if (lane == 4) { myv = g6; cell = 4; }
            else if (lane == 5) { myv = max(max(g4, g5), max(g6, g7)); cell = 5; }
            if (cell >= 0) {
                unsigned old = atom_max_rlx(&g_cellsB[cell], myv);
                if (old == 0xFFFFFFFFu) sh_red[11] = old;   // never true: forces completion
            }
            __syncwarp();
            if (lane == 0) {
                nbar++;
                unsigned o = atom_add_acqrel(&g_ctr[0], 1u);
                unsigned long long w;
                if (o == nbar * GB - 1u) {                  // last arriver
                    unsigned c0 = ld_rlx(&g_cellsB[0]), c1 = ld_rlx(&g_cellsB[1]);
                    unsigned c2 = ld_rlx(&g_cellsB[2]), c3 = ld_rlx(&g_cellsB[3]);
                    unsigned c4 = ld_rlx(&g_cellsB[4]), c5 = ld_rlx(&g_cellsB[5]);
                    st_rlx(&g_cellsB[0], 0u); st_rlx(&g_cellsB[1], 0u);
                    st_rlx(&g_cellsB[2], 0u); st_rlx(&g_cellsB[3], 0u);
                    st_rlx(&g_cellsB[4], 0u); st_rlx(&g_cellsB[5], 0u);
                    float mpi = unmapf(c0), mpf_ = unmapf(c1), mpg = unmapf(c2), mpo = unmapf(c3);
                    float mng = unmapf(c4), mna = unmapf(c5);
                    float mabs = fmaxf(fmaxf(fmaxf(mpi, mpf_), fmaxf(mpg, mpo)), mna);
                    int k1 = po2k(mabs);
                    float s1 = sc(k1), v1 = scinv(k1);
                    float ai = sigm(fq1(mpi, s1, v1));
                    float af = sigm(fq1(mpf_, s1, v1));
                    float ao = sigm(fq1(mpo, s1, v1));
                    float gqx = fq1(mpg, s1, v1), gqn = fq1(-mng, s1, v1);
                    float ag = tanhf(fmaxf(gqx, -gqn));
                    int ki = po2k(ai), kf = po2k(af), kg = po2k(ag), ko = po2k(ao);
                    w = ((unsigned long long)nbar << 40)
                      | (unsigned long long)(unsigned)(k1 + 128)
                      | ((unsigned long long)(unsigned)(ki + 128) << 8)
                      | ((unsigned long long)(unsigned)(kf + 128) << 16)
                      | ((unsigned long long)(unsigned)(kg + 128) << 24)
                      | ((unsigned long long)(unsigned)(ko + 128) << 32);
                    st_rel64(&g_bcB[0], w);
                } else {
                    do { w = ld_acq64(&g_bcB[0]); } while ((unsigned)(w >> 40) != nbar);
                }
                sh_k[0] = (int)((unsigned)w & 255u) - 128;
                sh_k[1] = (int)((unsigned)(w >> 8) & 255u) - 128;
                sh_k[2] = (int)((unsigned)(w >> 16) & 255u) - 128;
                sh_k[3] = (int)((unsigned)(w >> 24) & 255u) - 128;
                sh_k[4] = (int)((unsigned)(w >> 32) & 255u) - 128;
            }
        }
        __syncthreads();

        // ============ activations (scales already known) ============
        {
            int k1 = sh_k[0];
            float s1 = sc(k1), v1 = scinv(k1);
            int ka = sh_k[1 + gr];
            float sa = sc(ka), va = scinv(ka);
            float gq = fq1(pre, s1, v1);
            float act = (gr == 2) ? tanhf(gq) : sigm(gq);
            sh_act[tid] = fq1(act, sa, va);
        }
        __syncthreads();

        // ============ phase C: c update, tanh max + speculative h_pre max ============
        float tc = 0.0f, oq = 0.0f, hp = 0.0f;
        if (tid < 160) {
            float iq = sh_act[tid], ff = sh_act[tid + 160], gg = sh_act[tid + 320];
            oq = sh_act[tid + 480];
            c  = ff * c + iq * gg;
            tc = tanhf(c);
            hp = oq * fq1(tc, sc(k_pred), scinv(k_pred));
        }
        unsigned atw = warp_max_u(__float_as_uint(fabsf(tc)));
        unsigned ahw = warp_max_u(__float_as_uint(fabsf(hp)));
        if (lane == 0) { atomicMax(&sh_red[8], atw); atomicMax(&sh_red[9], ahw); }
        __syncthreads();

        if (wid == 0) {
            unsigned v = (lane < 2) ? sh_red[8 + lane] : 0u;
            __syncwarp();
            if (lane < 2) sh_red[8 + lane] = 0u;
            if (lane < 2) {
                unsigned old = atom_max_rlx(&g_cellsC[lane], v);
                if (old == 0xFFFFFFFFu) sh_red[11] = old;
            }
            __syncwarp();
            if (lane == 0) {
                nbar++;
                unsigned o = atom_add_acqrel(&g_ctr[0], 1u);
                unsigned long long w;
                if (o == nbar * GB - 1u) {
                    unsigned m0 = ld_rlx(&g_cellsC[0]), m1 = ld_rlx(&g_cellsC[1]);
                    st_rlx(&g_cellsC[0], 0u); st_rlx(&g_cellsC[1], 0u);
                    int k3 = po2k(__uint_as_float(m0));
                    unsigned hit = (k3 == k_pred) ? 1u : 0u;
                    int kh = hit ? po2k(__uint_as_float(m1)) : 0;
                    w = ((unsigned long long)nbar << 40)
                      | (unsigned long long)(unsigned)(k3 + 128)
                      | ((unsigned long long)(unsigned)(kh + 128) << 8)
                      | ((unsigned long long)hit << 16);
                    st_rel64(&g_bcC[0], w);
                } else {
                    do { w = ld_acq64(&g_bcC[0]); } while ((unsigned)(w >> 40) != nbar);
                }
                sh_k[0] = (int)((unsigned)w & 255u) - 128;
                sh_k[1] = (int)((unsigned)(w >> 8) & 255u) - 128;
                sh_k[2] = (int)((unsigned)(w >> 16) & 1u);
            }
        }
        __syncthreads();

        int k3 = sh_k[0], kh = sh_k[1], hit = sh_k[2];

        if (!hit) {
            // ---- rare fallback: recompute h_pre with actual tanh scale, reduce ----
            if (tid < 160) hp = oq * fq1(tc, sc(k3), scinv(k3));
            unsigned aw = warp_max_u(__float_as_uint(fabsf(hp)));
            if (lane == 0) atomicMax(&sh_red[10], aw);
            __syncthreads();
            if (wid == 0) {
                unsigned v = (lane == 0) ? sh_red[10] : 0u;
                __syncwarp();
                if (lane == 0) {
                    sh_red[10] = 0u;
                    unsigned old = atom_max_rlx(&g_cellsC[2], v);
                    if (old == 0xFFFFFFFFu) sh_red[11] = old;
                    nbar++;
                    unsigned o = atom_add_acqrel(&g_ctr[0], 1u);
                    unsigned long long w;
                    if (o == nbar * GB - 1u) {
                        unsigned m = ld_rlx(&g_cellsC[2]);
                        st_rlx(&g_cellsC[2], 0u);
                        int kh2 = po2k(__uint_as_float(m));
                        w = ((unsigned long long)nbar << 40)
                          | (unsigned long long)(unsigned)(kh2 + 128);
                        st_rel64(&g_bcD[0], w);
                    } else {
                        do { w = ld_acq64(&g_bcD[0]); } while ((unsigned)(w >> 40) != nbar);
                    }
                    sh_k[1] = (int)((unsigned)w & 255u) - 128;
                }
            }
            __syncthreads();
            kh = sh_k[1];
        }
        k_pred = k3;

        // ============ h quantize, publish, output ============
        if (tid < 160) {
            float hq = fq1(hp, sc(kh), scinv(kh));
            sh_h[b * NH + g] = hq;
            out[((size_t)(blockIdx.x * BPB + b) * T_STEPS + t) * NH + g] = hq;
        }
        if (tid < BPB * NI && t + 1 < T_STEPS) sh_x[tid] = xr;
        __syncthreads();
        if (tid < BPB * NI && t + 2 < T_STEPS)
            xr = x[((size_t)(blockIdx.x * BPB + xb) * T_STEPS + (t + 2)) * NI + xi];
    }
}

extern "C" void kernel_launch(void* const* d_in, const int* in_sizes, int n_in,
                              void* d_out, int out_size) {
    (void)in_sizes; (void)n_in; (void)out_size;
    qlstm_init<<<1, 64>>>();
    qlstm_main<<<GB, NT>>>((const float*)d_in[0],
                           (const float*)d_in[1],
                           (const float*)d_in[2],
                           (float*)d_out);
}

// round 6
// speedup vs baseline: 1.6313x; 1.5650x over previous
#include <cuda_runtime.h>

// ---------------------------------------------------------------------------
// Quantized LSTM, 2 grid barriers/step, leaderless barrier protocol:
//   red.relaxed.gpu.max into per-step pre-zeroed cells (one 256B line each)
//   -> atom.release.gpu.add on one counter -> pollers ld.acquire the counter
//   -> every block reads cells directly and derives all scales in parallel
//      (lane k of warp 0 handles cell k; activation scales via monotonicity).
// h-scale speculation on the tanh(c) exponent as in R4 (rare fallback barrier).
// ---------------------------------------------------------------------------

#define GB       128
#define BPB      8
#define NT       640
#define T_STEPS  1024
#define NI       10
#define NH       20
#define NG       80
#define CSTRIDE  64              // uints between cells = 256B (vary L2 hash bit 8)
#define NCELL    16              // cells reserved per step (9 used)

__device__ __align__(128) unsigned g_ctr[32];
__device__ unsigned g_cells[T_STEPS * NCELL * CSTRIDE];   // 4MB, only word 0 of each cell used

__global__ void qlstm_init() {
    int i = blockIdx.x * blockDim.x + threadIdx.x;   // 16384 threads = T_STEPS*NCELL
    if (i == 0) g_ctr[0] = 0u;
    if (i < T_STEPS * NCELL) g_cells[i * CSTRIDE] = 0u;
}

// order-preserving float<->uint key (signed max via unsigned max); key 0 = -inf-ish identity
__device__ __forceinline__ unsigned mapf(float f) {
    unsigned u = __float_as_uint(f);
    return (u & 0x80000000u) ? ~u : (u | 0x80000000u);
}
__device__ __forceinline__ float unmapf(unsigned u) {
    return __uint_as_float((u & 0x80000000u) ? (u & 0x7FFFFFFFu) : ~u);
}

// k = ceil(log2(max(m,1e-8))); scale = 2^(k-7), inv = 2^(7-k)
__device__ __forceinline__ int po2k(float m) {
    m = fmaxf(m, 1e-8f);
    int e; float f = frexpf(m, &e);
    return (f == 0.5f) ? (e - 1) : e;
}
__device__ __forceinline__ float sc(int k)    { return __uint_as_float((unsigned)(k + 120) << 23); }
__device__ __forceinline__ float scinv(int k) { return __uint_as_float((unsigned)(134 - k) << 23); }

__device__ __forceinline__ float fq1(float x, float s, float inv) {
    float q = rintf(x * inv);
    q = fminf(fmaxf(q, -128.0f), 127.0f);
    return q * s;
}
__device__ __forceinline__ float sigm(float x) { return 1.0f / (1.0f + expf(-x)); }

__device__ __forceinline__ unsigned warp_max_u(unsigned v) {
#pragma unroll
    for (int o = 16; o; o >>= 1) v = max(v, __shfl_xor_sync(0xffffffffu, v, o));
    return v;
}

__device__ __forceinline__ void red_max_rlx(unsigned* p, unsigned v) {
    asm volatile("red.relaxed.gpu.max.u32 [%0],%1;" :: "l"(p), "r"(v) : "memory");
}
__device__ __forceinline__ unsigned atom_add_rel(unsigned* p, unsigned v) {
    unsigned old;
    asm volatile("atom.release.gpu.add.u32 %0,[%1],%2;" : "=r"(old) : "l"(p), "r"(v) : "memory");
    return old;
}
__device__ __forceinline__ unsigned ld_acq(const unsigned* p) {
    unsigned v; asm volatile("ld.acquire.gpu.u32 %0,[%1];" : "=r"(v) : "l"(p) : "memory"); return v;
}
__device__ __forceinline__ unsigned ld_rlx(const unsigned* p) {
    unsigned v; asm volatile("ld.relaxed.gpu.u32 %0,[%1];" : "=r"(v) : "l"(p) : "memory"); return v;
}

__global__ void __launch_bounds__(NT, 1) qlstm_main(
    const float* __restrict__ x,
    const float* __restrict__ Wih,
    const float* __restrict__ Whh,
    float* __restrict__ out)
{
    __shared__ __align__(16) float sh_h[BPB * NH];
    __shared__ __align__(16) float sh_x[BPB * NI];
    __shared__ float               sh_act[NG * BPB];
    __shared__ unsigned            sh_red[12];   // B:[0..7]  C:[8,9]  D:[10]  wscale:[11]
    __shared__ int                 sh_k[8];

    const int tid  = threadIdx.x;
    const int g    = tid / BPB;          // gate row 0..79
    const int b    = tid % BPB;          // local batch 0..7
    const int gr   = tid / 160;          // gate group 0..3 (warp-uniform)
    const int lane = tid & 31;
    const int wid  = tid >> 5;

    if (tid < 12) sh_red[tid] = 0u;
    if (tid < BPB * NH) sh_h[tid] = 0.0f;
    __syncthreads();

    // ---- weight scale (block-local, once) ----
    {
        float wm = 0.0f;
        for (int k = tid; k < NG * NI; k += NT) wm = fmaxf(wm, fabsf(Wih[k]));
        for (int k = tid; k < NG * NH; k += NT) wm = fmaxf(wm, fabsf(Whh[k]));
        unsigned u = warp_max_u(__float_as_uint(wm));
        if (lane == 0) atomicMax(&sh_red[11], u);
        __syncthreads();
    }
    int kw = po2k(__uint_as_float(sh_red[11]));
    float ws = sc(kw), wsi = scinv(kw);

    float wi[NI], wh[NH];
#pragma unroll
    for (int i2 = 0; i2 < NI; i2++) wi[i2] = fq1(Wih[g * NI + i2], ws, wsi);
#pragma unroll
    for (int j2 = 0; j2 < NH; j2++) wh[j2] = fq1(Whh[g * NH + j2], ws, wsi);

    float    c = 0.0f;
    int      k_pred = 0;
    unsigned nbar = 0;

    // x staging owned by warps 17-19 (threads 560..639), idle during barriers
    const int sq  = tid - 560;                 // 0..79 when tid>=560
    const int sxb = (sq >= 0) ? sq / NI : 0;
    const int sxi = (sq >= 0) ? sq % NI : 0;
    float xr = 0.0f;
    if (sq >= 0) {
        sh_x[sq] = x[((size_t)(blockIdx.x * BPB + sxb) * T_STEPS + 0) * NI + sxi];
        xr       = x[((size_t)(blockIdx.x * BPB + sxb) * T_STEPS + 1) * NI + sxi];
    }
    __syncthreads();

    for (int t = 0; t < T_STEPS; ++t) {
        // ===== phase B: pre-activations + signed per-group min/max =====
        float p0 = 0.0f, p1 = 0.0f;
        {
            const float2* px = reinterpret_cast<const float2*>(&sh_x[b * NI]);
            const float2* ph = reinterpret_cast<const float2*>(&sh_h[b * NH]);
#pragma unroll
            for (int j = 0; j < NI / 2; j++) {
                float2 v = px[j];
                p0 = fmaf(v.x, wi[2 * j], p0); p1 = fmaf(v.y, wi[2 * j + 1], p1);
            }
#pragma unroll
            for (int j = 0; j < NH / 2; j++) {
                float2 v = ph[j];
                p0 = fmaf(v.x, wh[2 * j], p0); p1 = fmaf(v.y, wh[2 * j + 1], p1);
            }
        }
        float pre = p0 + p1;

        unsigned kp = warp_max_u(mapf(pre));
        unsigned kn = warp_max_u(mapf(-pre));
        if (lane == 0) { atomicMax(&sh_red[gr], kp); atomicMax(&sh_red[4 + gr], kn); }
        __syncthreads();                                        // S1

        if (sq >= 0 && t + 1 < T_STEPS) sh_x[sq] = xr;          // stage next x (read post-S2)

        if (wid == 0) {
            unsigned v = (lane < 8) ? sh_red[lane] : 0u;
            __syncwarp();
            if (lane < 8) sh_red[lane] = 0u;
            unsigned n0 = __shfl_sync(0xffffffffu, v, 4);
            unsigned n1 = __shfl_sync(0xffffffffu, v, 5);
            unsigned n2 = __shfl_sync(0xffffffffu, v, 6);
            unsigned n3 = __shfl_sync(0xffffffffu, v, 7);
            unsigned myv = v;
            if (lane == 4) myv = n2;                            // max(-pre) of tanh group
            if (lane == 5) myv = max(max(n0, n1), max(n2, n3)); // max(-pre) global
            unsigned* cb = &g_cells[(t * NCELL) * CSTRIDE];
            if (lane < 6) red_max_rlx(cb + lane * CSTRIDE, myv);
            nbar++;
            unsigned tgt = nbar * GB, last = 0;
            if (lane == 0) last = (atom_add_rel(&g_ctr[0], 1u) == tgt - 1u);
            last = __shfl_sync(0xffffffffu, last, 0);
            if (!last && lane < 6) { while (ld_acq(&g_ctr[0]) < tgt) { } }
            __syncwarp();
            unsigned cv = (lane < 6) ? ld_rlx(cb + lane * CSTRIDE) : 0u;
            unsigned kk = (lane == 4 || lane >= 6) ? 0u : cv;   // exclude cell4 from |pre| max
#pragma unroll
            for (int o = 4; o; o >>= 1) kk = max(kk, __shfl_xor_sync(0xffffffffu, kk, o));
            int k1 = po2k(unmapf(kk));
            float s1 = sc(k1), v1 = scinv(k1);
            float mng = unmapf(__shfl_sync(0xffffffffu, cv, 4));
            float myp = unmapf(cv);
            float a;
            if (lane == 2) {
                float q1 = fq1(myp, s1, v1), q2 = fq1(-mng, s1, v1);
                a = tanhf(fmaxf(q1, -q2));
            } else {
                a = sigm(fq1(myp, s1, v1));
            }
            int ka = po2k(fabsf(a));
            if (lane == 0) sh_k[0] = k1;
            if (lane < 4)  sh_k[1 + lane] = ka;
        }
        __syncthreads();                                        // S2

        // ===== activations (all scales known, derived in parallel) =====
        {
            int k1 = sh_k[0];
            int ka = sh_k[1 + gr];
            float gq  = fq1(pre, sc(k1), scinv(k1));
            float act = (gr == 2) ? tanhf(gq) : sigm(gq);
            sh_act[tid] = fq1(act, sc(ka), scinv(ka));
        }
        if (sq >= 0 && t + 2 < T_STEPS)                          // prefetch t+2
            xr = x[((size_t)(blockIdx.x * BPB + sxb) * T_STEPS + (t + 2)) * NI + sxi];
        __syncthreads();                                        // S3

        // ===== phase C: c update, max|tanh c| + speculative max|h_pre| =====
        float tc = 0.0f, oq = 0.0f, hp = 0.0f;
        if (tid < 160) {
            float iq = sh_act[tid], ff = sh_act[tid + 160], gg = sh_act[tid + 320];
            oq = sh_act[tid + 480];
            c  = ff * c + iq * gg;
            tc = tanhf(c);
            hp = oq * fq1(tc, sc(k_pred), scinv(k_pred));
        }
        if (wid < 5) {
            unsigned a1 = warp_max_u(__float_as_uint(fabsf(tc)));
            unsigned a2 = warp_max_u(__float_as_uint(fabsf(hp)));
            if (lane == 0) { atomicMax(&sh_red[8], a1); atomicMax(&sh_red[9], a2); }
        }
        __syncthreads();                                        // S4

        if (wid == 0) {
            unsigned v = (lane < 2) ? sh_red[8 + lane] : 0u;
            __syncwarp();
            if (lane < 2) sh_red[8 + lane] = 0u;
            unsigned* cb = &g_cells[(t * NCELL + 6) * CSTRIDE];
            if (lane < 2) red_max_rlx(cb + lane * CSTRIDE, v);
            nbar++;
            unsigned tgt = nbar * GB, last = 0;
            if (lane == 0) last = (atom_add_rel(&g_ctr[0], 1u) == tgt - 1u);
            last = __shfl_sync(0xffffffffu, last, 0);
            if (!last && lane < 2) { while (ld_acq(&g_ctr[0]) < tgt) { } }
            __syncwarp();
            unsigned cv = (lane < 2) ? ld_rlx(cb + lane * CSTRIDE) : 0u;
            int kx = po2k(__uint_as_float(cv));                  // lane0: k3, lane1: kh_spec
            int k3 = __shfl_sync(0xffffffffu, kx, 0);
            if (lane == 0) { sh_k[0] = k3; sh_k[2] = (k3 == k_pred); }
            if (lane == 1) sh_k[1] = kx;
        }
        __syncthreads();                                        // S5

        int k3 = sh_k[0], kh = sh_k[1], hit = sh_k[2];

        if (!hit) {   // rare: tanh-scale prediction missed; redo h_pre max (uniform across blocks)
            if (tid < 160) hp = oq * fq1(tc, sc(k3), scinv(k3));
            if (wid < 5) {
                unsigned aw = warp_max_u(__float_as_uint(fabsf(hp)));
                if (lane == 0) atomicMax(&sh_red[10], aw);
            }
            __syncthreads();
            if (wid == 0) {
                unsigned v = (lane == 0) ? sh_red[10] : 0u;
                __syncwarp();
                if (lane == 0) sh_red[10] = 0u;
                unsigned* cb = &g_cells[(t * NCELL + 8) * CSTRIDE];
                if (lane == 0) red_max_rlx(cb, v);
                nbar++;
                unsigned tgt = nbar * GB, last = 0;
                if (lane == 0) last = (atom_add_rel(&g_ctr[0], 1u) == tgt - 1u);
                last = __shfl_sync(0xffffffffu, last, 0);
                if (!last && lane == 0) { while (ld_acq(&g_ctr[0]) < tgt) { } }
                __syncwarp();
                if (lane == 0) sh_k[1] = po2k(__uint_as_float(ld_rlx(cb)));
            }
            __syncthreads();
            kh = sh_k[1];
        }
        k_pred = k3;

        // ===== h quantize, publish, output =====
        if (tid < 160) {
            float hq = fq1(hp, sc(kh), scinv(kh));
            sh_h[b * NH + g] = hq;
            out[((size_t)(blockIdx.x * BPB + b) * T_STEPS + t) * NH + g] = hq;
        }
        __syncthreads();                                        // S6
    }
}

extern "C" void kernel_launch(void* const* d_in, const int* in_sizes, int n_in,
                              void* d_out, int out_size) {
    (void)in_sizes; (void)n_in; (void)out_size;
    qlstm_init<<<32, 512>>>();
    qlstm_main<<<GB, NT>>>((const float*)d_in[0],
                           (const float*)d_in[1],
                           (const float*)d_in[2],
                           (float*)d_out);
}

// round 7
// speedup vs baseline: 1.9688x; 1.2069x over previous
#include <cuda_runtime.h>

// ---------------------------------------------------------------------------
// Quantized LSTM, ONE grid barrier per step (steady state) via full scale
// speculation: predict all 6 po2 exponents from the previous step, compute
// pre -> act_q -> c -> tanh(c) -> h_pre speculatively, then one barrier
// reduces {per-group signed min/max of pre, max|tanh c|, max|h_pre|} and
// verifies every prediction (activation scales derived analytically from the
// group extrema by monotonicity). Globally-uniform fallback re-barriers on miss.
// ---------------------------------------------------------------------------

#define GB       128
#define BPB      8
#define NT       640
#define T_STEPS  1024
#define NI       10
#define NH       20
#define NG       80
#define CSTRIDE  64              // 256B between cells (vary L2 hash)
#define NCELL    16              // slots/step: 0-7 main, 8 c1, 9-10 c2a, 11 c2b

__device__ __align__(128) unsigned g_ctr[32];
__device__ unsigned g_cells[T_STEPS * NCELL * CSTRIDE];   // word 0 of each cell used

__global__ void qlstm_init() {
    int i = blockIdx.x * blockDim.x + threadIdx.x;   // 16384 = T_STEPS*NCELL
    if (i == 0) g_ctr[0] = 0u;
    if (i < T_STEPS * NCELL) g_cells[i * CSTRIDE] = 0u;
}

// order-preserving float<->uint key
__device__ __forceinline__ unsigned mapf(float f) {
    unsigned u = __float_as_uint(f);
    return (u & 0x80000000u) ? ~u : (u | 0x80000000u);
}
__device__ __forceinline__ float unmapf(unsigned u) {
    return __uint_as_float((u & 0x80000000u) ? (u & 0x7FFFFFFFu) : ~u);
}
// k = ceil(log2(max(m,1e-8))); scale = 2^(k-7)
__device__ __forceinline__ int po2k(float m) {
    m = fmaxf(m, 1e-8f);
    int e; float f = frexpf(m, &e);
    return (f == 0.5f) ? (e - 1) : e;
}
__device__ __forceinline__ float sc(int k)    { return __uint_as_float((unsigned)(k + 120) << 23); }
__device__ __forceinline__ float scinv(int k) { return __uint_as_float((unsigned)(134 - k) << 23); }
__device__ __forceinline__ float fq1(float x, float s, float inv) {
    float q = rintf(x * inv);
    q = fminf(fmaxf(q, -128.0f), 127.0f);
    return q * s;
}
__device__ __forceinline__ float sigm(float x) { return 1.0f / (1.0f + expf(-x)); }
__device__ __forceinline__ unsigned warp_max_u(unsigned v) {
#pragma unroll
    for (int o = 16; o; o >>= 1) v = max(v, __shfl_xor_sync(0xffffffffu, v, o));
    return v;
}
__device__ __forceinline__ void red_max_rlx(unsigned* p, unsigned v) {
    asm volatile("red.relaxed.gpu.max.u32 [%0],%1;" :: "l"(p), "r"(v) : "memory");
}
__device__ __forceinline__ unsigned atom_add_acqrel(unsigned* p, unsigned v) {
    unsigned old;
    asm volatile("atom.acq_rel.gpu.add.u32 %0,[%1],%2;" : "=r"(old) : "l"(p), "r"(v) : "memory");
    return old;
}
__device__ __forceinline__ unsigned ld_acq(const unsigned* p) {
    unsigned v; asm volatile("ld.acquire.gpu.u32 %0,[%1];" : "=r"(v) : "l"(p) : "memory"); return v;
}
__device__ __forceinline__ unsigned ld_rlx(const unsigned* p) {
    unsigned v; asm volatile("ld.relaxed.gpu.u32 %0,[%1];" : "=r"(v) : "l"(p) : "memory"); return v;
}

// warp0-collective grid barrier: lane<ncontrib reds myv into cell[lane], one
// acq_rel counter add, poll, return this lane's cell value.
__device__ __forceinline__ unsigned grid_bar(unsigned* cb, unsigned myv, int ncontrib,
                                             unsigned tgt, int lane) {
    if (lane < ncontrib) red_max_rlx(cb + lane * CSTRIDE, myv);
    __syncwarp();
    unsigned last = 0;
    if (lane == 0) last = (atom_add_acqrel(&g_ctr[0], 1u) == tgt - 1u) ? 1u : 0u;
    last = __shfl_sync(0xffffffffu, last, 0);
    if (!last) { while (ld_acq(&g_ctr[0]) < tgt) { } }
    __syncwarp();
    return (lane < ncontrib) ? ld_rlx(cb + lane * CSTRIDE) : 0u;
}

__global__ void __launch_bounds__(NT, 1) qlstm_main(
    const float* __restrict__ x,
    const float* __restrict__ Wih,
    const float* __restrict__ Whh,
    float* __restrict__ out)
{
    __shared__ __align__(16) float sh_h[BPB * NH];
    __shared__ __align__(16) float sh_x[BPB * NI];
    __shared__ float               sh_act[NG * BPB];
    __shared__ unsigned            sh_red[12];
    __shared__ int                 sh_k[10];   // 0:k1 1-4:ka 5:k3 6:kh 7:code 8:hit3b
    __shared__ int                 sh_kp[6];   // predictions: k1,ka0-3,k3

    const int tid  = threadIdx.x;
    const int g    = tid / BPB;
    const int b    = tid % BPB;
    const int gr   = tid / 160;          // warp-uniform gate group
    const int lane = tid & 31;
    const int wid  = tid >> 5;

    if (tid < 12) sh_red[tid] = 0u;
    if (tid < 6)  sh_kp[tid] = 99;       // force full miss at t=0
    if (tid < BPB * NH) sh_h[tid] = 0.0f;
    __syncthreads();

    // ---- weight scale (block-local, once) ----
    {
        float wm = 0.0f;
        for (int k = tid; k < NG * NI; k += NT) wm = fmaxf(wm, fabsf(Wih[k]));
        for (int k = tid; k < NG * NH; k += NT) wm = fmaxf(wm, fabsf(Whh[k]));
        unsigned u = warp_max_u(__float_as_uint(wm));
        if (lane == 0) atomicMax(&sh_red[11], u);
        __syncthreads();
    }
    int kw = po2k(__uint_as_float(sh_red[11]));
    float ws = sc(kw), wsi = scinv(kw);
    __syncthreads();
    if (tid == 0) sh_red[11] = 0u;

    float wi[NI], wh[NH];
#pragma unroll
    for (int i2 = 0; i2 < NI; i2++) wi[i2] = fq1(Wih[g * NI + i2], ws, wsi);
#pragma unroll
    for (int j2 = 0; j2 < NH; j2++) wh[j2] = fq1(Whh[g * NH + j2], ws, wsi);

    float    c = 0.0f, c_prev = 0.0f;
    unsigned nbar = 0;

    const int sq  = tid - 560;                 // warps 17-19 stage x
    const int sxb = (sq >= 0) ? sq / NI : 0;
    const int sxi = (sq >= 0) ? sq % NI : 0;
    float xr = 0.0f;
    if (sq >= 0) {
        sh_x[sq] = x[((size_t)(blockIdx.x * BPB + sxb) * T_STEPS + 0) * NI + sxi];
        xr       = x[((size_t)(blockIdx.x * BPB + sxb) * T_STEPS + 1) * NI + sxi];
    }
    __syncthreads();

    for (int t = 0; t < T_STEPS; ++t) {
        const int k1p = sh_kp[0];
        const int kap = sh_kp[1 + gr];
        const int k3p = sh_kp[5];

        // ===== speculative phase 1: pre, group min/max, activations =====
        float p0 = 0.0f, p1 = 0.0f;
        {
            const float2* px = reinterpret_cast<const float2*>(&sh_x[b * NI]);
            const float2* ph = reinterpret_cast<const float2*>(&sh_h[b * NH]);
#pragma unroll
            for (int j = 0; j < NI / 2; j++) {
                float2 v = px[j];
                p0 = fmaf(v.x, wi[2 * j], p0); p1 = fmaf(v.y, wi[2 * j + 1], p1);
            }
#pragma unroll
            for (int j = 0; j < NH / 2; j++) {
                float2 v = ph[j];
                p0 = fmaf(v.x, wh[2 * j], p0); p1 = fmaf(v.y, wh[2 * j + 1], p1);
            }
        }
        float pre = p0 + p1;

        unsigned kp = warp_max_u(mapf(pre));
        unsigned kn = warp_max_u(mapf(-pre));
        if (lane == 0) { atomicMax(&sh_red[gr], kp); atomicMax(&sh_red[4 + gr], kn); }

        {
            float gq  = fq1(pre, sc(k1p), scinv(k1p));
            float act = (gr == 2) ? tanhf(gq) : sigm(gq);
            sh_act[tid] = fq1(act, sc(kap), scinv(kap));
        }
        __syncthreads();                                        // S1
        if (sq >= 0 && t + 1 < T_STEPS) sh_x[sq] = xr;

        // ===== speculative phase 2: c update, tanh, h_pre =====
        float tc = 0.0f, oq = 0.0f, hp = 0.0f;
        if (tid < 160) {
            float iq = sh_act[tid], ff = sh_act[tid + 160], gg = sh_act[tid + 320];
            oq = sh_act[tid + 480];
            c_prev = c;
            c  = ff * c + iq * gg;
            tc = tanhf(c);
            hp = oq * fq1(tc, sc(k3p), scinv(k3p));
        }
        if (wid < 5) {
            unsigned a1 = warp_max_u(__float_as_uint(fabsf(tc)));
            unsigned a2 = warp_max_u(__float_as_uint(fabsf(hp)));
            if (lane == 0) { atomicMax(&sh_red[8], a1); atomicMax(&sh_red[9], a2); }
        }
        if (sq >= 0 && t + 2 < T_STEPS)
            xr = x[((size_t)(blockIdx.x * BPB + sxb) * T_STEPS + (t + 2)) * NI + sxi];
        __syncthreads();                                        // S2

        unsigned* cb = &g_cells[(size_t)t * NCELL * CSTRIDE];

        // ===== single grid barrier: reduce + verify everything =====
        if (wid == 0) {
            unsigned v = (lane < 10) ? sh_red[lane] : 0u;
            __syncwarp();
            if (lane < 10) sh_red[lane] = 0u;
            unsigned n0 = __shfl_sync(0xffffffffu, v, 4);
            unsigned n1 = __shfl_sync(0xffffffffu, v, 5);
            unsigned n2 = __shfl_sync(0xffffffffu, v, 6);
            unsigned n3 = __shfl_sync(0xffffffffu, v, 7);
            unsigned t8 = __shfl_sync(0xffffffffu, v, 8);
            unsigned t9 = __shfl_sync(0xffffffffu, v, 9);
            unsigned myv = v;                                   // lanes 0-3: group max(pre)
            if (lane == 4) myv = n2;                            // max(-pre) tanh group
            if (lane == 5) myv = max(max(n0, n1), max(n2, n3)); // global max(-pre)
            if (lane == 6) myv = t8;                            // max|tanh c|
            if (lane == 7) myv = t9;                            // max|h_pre spec|
            nbar++;
            unsigned cv = grid_bar(cb, myv, 8, nbar * GB, lane);

            unsigned kk = (lane < 4 || lane == 5) ? cv : 0u;    // |pre| max over octet
            kk = max(kk, __shfl_xor_sync(0xffffffffu, kk, 4));
            kk = max(kk, __shfl_xor_sync(0xffffffffu, kk, 2));
            kk = max(kk, __shfl_xor_sync(0xffffffffu, kk, 1));
            int k1 = po2k(unmapf(kk));
            float s1 = sc(k1), v1 = scinv(k1);
            float mng = unmapf(__shfl_sync(0xffffffffu, cv, 4));
            float myp = unmapf(cv);
            float a;
            if (lane == 2) {
                float q1 = fq1(myp, s1, v1), q2 = fq1(-mng, s1, v1);
                a = tanhf(fmaxf(q1, -q2));
            } else {
                a = sigm(fq1(myp, s1, v1));
            }
            int ka  = po2k(fabsf(a));
            int k3t = po2k(__uint_as_float(__shfl_sync(0xffffffffu, cv, 6)));
            int kht = po2k(__uint_as_float(__shfl_sync(0xffffffffu, cv, 7)));

            bool okl = (lane < 4) ? (ka == sh_kp[1 + lane]) : true;
            unsigned bm = __ballot_sync(0xffffffffu, okl);
            int hit1 = ((bm & 0xFu) == 0xFu) && (k1 == sh_kp[0]);
            int hit3 = (k3t == sh_kp[5]);
            if (lane < 4) { sh_k[1 + lane] = ka; }
            if (lane == 0) {
                sh_k[0] = k1; sh_k[5] = k3t; sh_k[6] = kht;
                sh_k[7] = hit1 ? (hit3 ? 0 : 1) : 2;
                sh_kp[0] = k1;
                if (hit1) sh_kp[5] = k3t;
            }
            if (lane < 4) sh_kp[1 + lane] = ka;
        }
        __syncthreads();                                        // S3

        const int code = sh_k[7];
        if (code == 0) {
            // ---- full hit: everything already computed ----
            if (tid < 160) {
                int kh = sh_k[6];
                float hq = fq1(hp, sc(kh), scinv(kh));
                sh_h[b * NH + g] = hq;
                out[((size_t)(blockIdx.x * BPB + b) * T_STEPS + t) * NH + g] = hq;
            }
        } else if (code == 1) {
            // ---- k3 miss only (c, tc valid): redo h_pre with true k3 ----
            int k3 = sh_k[5];
            if (tid < 160) hp = oq * fq1(tc, sc(k3), scinv(k3));
            if (wid < 5) {
                unsigned aw = warp_max_u(__float_as_uint(fabsf(hp)));
                if (lane == 0) atomicMax(&sh_red[10], aw);
            }
            __syncthreads();
            if (wid == 0) {
                unsigned v = (lane == 0) ? sh_red[10] : 0u;
                __syncwarp();
                if (lane == 0) sh_red[10] = 0u;
                nbar++;
                unsigned cv = grid_bar(cb + 8 * CSTRIDE, v, 1, nbar * GB, lane);
                if (lane == 0) sh_k[6] = po2k(__uint_as_float(cv));
            }
            __syncthreads();
            if (tid < 160) {
                int kh = sh_k[6];
                float hq = fq1(hp, sc(kh), scinv(kh));
                sh_h[b * NH + g] = hq;
                out[((size_t)(blockIdx.x * BPB + b) * T_STEPS + t) * NH + g] = hq;
            }
        } else {
            // ---- full miss: recompute with true k1/ka from the reduced extrema ----
            {
                int k1 = sh_k[0], kat = sh_k[1 + gr];
                float gq  = fq1(pre, sc(k1), scinv(k1));
                float act = (gr == 2) ? tanhf(gq) : sigm(gq);
                sh_act[tid] = fq1(act, sc(kat), scinv(kat));
            }
            __syncthreads();
            if (tid < 160) {
                float iq = sh_act[tid], ff = sh_act[tid + 160], gg = sh_act[tid + 320];
                oq = sh_act[tid + 480];
                c  = ff * c_prev + iq * gg;
                tc = tanhf(c);
                hp = oq * fq1(tc, sc(k3p), scinv(k3p));
            }
            if (wid < 5) {
                unsigned a1 = warp_max_u(__float_as_uint(fabsf(tc)));
                unsigned a2 = warp_max_u(__float_as_uint(fabsf(hp)));
                if (lane == 0) { atomicMax(&sh_red[10], a1); atomicMax(&sh_red[11], a2); }
            }
            __syncthreads();
            if (wid == 0) {
                unsigned v = (lane < 2) ? sh_red[10 + lane] : 0u;
                __syncwarp();
                if (lane < 2) sh_red[10 + lane] = 0u;
                nbar++;
                unsigned cv = grid_bar(cb + 9 * CSTRIDE, v, 2, nbar * GB, lane);
                int kx = po2k(__uint_as_float(cv));
                int k3 = __shfl_sync(0xffffffffu, kx, 0);
                int kh = __shfl_sync(0xffffffffu, kx, 1);
                if (lane == 0) {
                    sh_k[5] = k3; sh_k[6] = kh; sh_k[8] = (k3 == k3p);
                    sh_kp[5] = k3;
                }
            }
            __syncthreads();
            if (!sh_k[8]) {   // k3 prediction also missed: one more round
                int k3 = sh_k[5];
                if (tid < 160) hp = oq * fq1(tc, sc(k3), scinv(k3));
                if (wid < 5) {
                    unsigned aw = warp_max_u(__float_as_uint(fabsf(hp)));
                    if (lane == 0) atomicMax(&sh_red[10], aw);
                }
                __syncthreads();
                if (wid == 0) {
                    unsigned v = (lane == 0) ? sh_red[10] : 0u;
                    __syncwarp();
                    if (lane == 0) sh_red[10] = 0u;
                    nbar++;
                    unsigned cv = grid_bar(cb + 11 * CSTRIDE, v, 1, nbar * GB, lane);
                    if (lane == 0) sh_k[6] = po2k(__uint_as_float(cv));
                }
                __syncthreads();
            }
            if (tid < 160) {
                int kh = sh_k[6];
                float hq = fq1(hp, sc(kh), scinv(kh));
                sh_h[b * NH + g] = hq;
                out[((size_t)(blockIdx.x * BPB + b) * T_STEPS + t) * NH + g] = hq;
            }
        }
        __syncthreads();                                        // S4
    }
}

extern "C" void kernel_launch(void* const* d_in, const int* in_sizes, int n_in,
                              void* d_out, int out_size) {
    (void)in_sizes; (void)n_in; (void)out_size;
    qlstm_init<<<32, 512>>>();
    qlstm_main<<<GB, NT>>>((const float*)d_in[0],
                           (const float*)d_in[1],
                           (const float*)d_in[2],
                           (float*)d_out);
}